// round 13
// baseline (speedup 1.0000x reference)
#include <cuda_runtime.h>
#include <cuda_fp16.h>
#include <cstdint>

// ---------------------------------------------------------------------------
// Scratch (static __device__ globals; no allocation allowed)
// ---------------------------------------------------------------------------
__device__ float    g_bufA[33554432];   // ping: fp16 hi/lo planes (as halves)
__device__ float    g_bufB[33554432];   // pong
__device__ float    g_bufP[16777216];   // split-K fp32 partials
__device__ float    g_bufC[1048576];    // fp32 inner activations (BN input)
__device__ float    g_bufX[8388608];    // input hi/lo planes, C padded to 16
__device__ uint4    g_w4[5504256];      // fused B-fragment weights (hi,hi,lo,lo)
__device__ float    g_mean[1024];
__device__ float    g_rstd[1024];

// fused-repack layer tables (element = one uint4 = 4 weights hi+lo)
__constant__ int rk_ci[11]  = {3, 64, 128, 256, 512, 1024, 1024, 512, 256, 128, 64};
__constant__ int rk_cip[11] = {16, 64, 128, 256, 512, 1024, 1024, 512, 256, 128, 64};
__constant__ int rk_co[11]  = {64, 128, 256, 512, 1024, 1024, 512, 256, 128, 64, 64};
// offsets: cumulative 9*(Cip/16)*4*Co per layer (VERIFIED against host off[])
__constant__ int rk_offs[12] = {0, 2304, 20736, 94464, 389376, 1569024, 3928320,
                                5107968, 5402880, 5476608, 5495040, 5504256};

__device__ __forceinline__ float lrelu(float v) { return v >= 0.f ? v : 0.01f * v; }

__device__ __forceinline__ void cp16(uint32_t dst, const void* src, int sz)
{
    asm volatile("cp.async.cg.shared.global [%0], [%1], 16, %2;"
                 :: "r"(dst), "l"(src), "r"(sz));
}
__device__ __forceinline__ void cp_commit()
{
    asm volatile("cp.async.commit_group;");
}
template <int N>
__device__ __forceinline__ void cp_wait_n()
{
    asm volatile("cp.async.wait_group %0;" :: "n"(N));
}

__device__ __forceinline__ void ldsm4(uint32_t& r0, uint32_t& r1, uint32_t& r2,
                                      uint32_t& r3, uint32_t addr)
{
    asm volatile("ldmatrix.sync.aligned.m8n8.x4.shared.b16 {%0,%1,%2,%3}, [%4];"
                 : "=r"(r0), "=r"(r1), "=r"(r2), "=r"(r3) : "r"(addr));
}

__device__ __forceinline__ void mma16816(float* acc, uint32_t a0, uint32_t a1,
                                         uint32_t a2, uint32_t a3, uint32_t b0, uint32_t b1)
{
    asm volatile("mma.sync.aligned.m16n8k16.row.col.f32.f16.f16.f32 "
                 "{%0,%1,%2,%3},{%4,%5,%6,%7},{%8,%9},{%0,%1,%2,%3};"
                 : "+f"(acc[0]), "+f"(acc[1]), "+f"(acc[2]), "+f"(acc[3])
                 : "r"(a0), "r"(a1), "r"(a2), "r"(a3), "r"(b0), "r"(b1));
}

__device__ __forceinline__ void split16(float v, __half& h, __half& l)
{
    h = __float2half_rn(v);
    l = __float2half_rn(v - __half2float(h));
}

// ---------------------------------------------------------------------------
// Tensor-core implicit-GEMM conv (NHWC fp16 hi/lo planes), 3-term fp16 split.
// MF = M-fragments per warp. N tile = 64 co. DB = staging buffers.
// MODE 0: SAME conv + stride-2 subsample. Even/odd column-plane patch so
//         stride-2 A ldmatrix reads are conflict-free.
// MODE 1: SAME conv stride 1
// MODE 2 (MERGED): zero-insert up2 + SAME conv, ALL 4 parity classes in one
//         block (4 accumulator sets; 9 taps grouped by the 4 shared patch
//         offsets {0,1,9,10}); block covers 16x16 outputs per 8x8 quad tile.
//         MF must be 1.
// Block: 256 thr = 8 warps (4 M x 2 N). K-chunk 16 channels.
// ---------------------------------------------------------------------------
template <int MODE, int SPLIT, int MF, int DB>
__global__ void __launch_bounds__(256, 2) conv_tc(
    const __half* __restrict__ inHi, const __half* __restrict__ inLo,
    const uint4* __restrict__ w4, const float* __restrict__ bias,
    __half* __restrict__ outHi, __half* __restrict__ outLo,
    float* __restrict__ outP,
    int NB, int Ci, int Co, int Hout, int Wout, int act)
{
    constexpr int PW   = (MODE == 0) ? 17 : ((MODE == 1) ? 10 : 9);
    constexpr int PH   = (MODE == 0) ? (16 * MF + 1) : ((MODE == 1) ? (8 * MF + 2) : (8 * MF + 1));
    constexpr int NPX  = PH * PW;
    constexpr int CSTR = 24;                       // halves per pixel row (16 used)
    constexpr int MAXT = 9;
    constexpr int MDEL = ((MODE == 0) ? 16 : 8) * PW * CSTR * 2;  // byte delta between M-fragments
    constexpr int PATB = NPX * CSTR * 2;           // one plane bytes
    constexpr int WOFF = 2 * PATB;                 // weights offset inside buffer
    constexpr int BUFSZ = WOFF + MAXT * 256 * 16;  // one staging buffer bytes
    constexpr int NACC = (MODE == 2) ? 4 : MF;     // accumulator sets

    // MODE 2 tap->class and offset-group tables (compile-time)
    // cls(t) = (1-(kh&1))*2 + (1-(kw&1));  toff group = (kh>>1)*PW + (kw>>1)
    constexpr int gcnt[4]    = {4, 2, 2, 1};
    constexpr int gtoff[4]   = {0, 1, 9, 10};
    constexpr int gtap[4][4] = {{0, 1, 3, 4}, {2, 5, 0, 0}, {6, 7, 0, 0}, {8, 0, 0, 0}};
    constexpr int clsOf[9]   = {3, 2, 3, 1, 0, 1, 3, 2, 3};

    extern __shared__ __align__(16) char smem[];

    const int tid  = threadIdx.x;
    const int lane = tid & 31, w = tid >> 5;
    const int g    = lane >> 2, tig = lane & 3;
    const int wm   = w & 3, wn = w >> 2;

    const int SX    = (MODE == 2) ? (Wout >> 4) : (Wout >> 3);
    const int sx    = blockIdx.x % SX;
    const int split = blockIdx.x / SX;
    const int sy    = blockIdx.y;
    const int gpc   = Co >> 6;
    const int z     = blockIdx.z;
    const int n     = z / gpc;
    const int cob   = (z - n * gpc) << 6;

    int Hin, Win, iy0, ix0;
    if (MODE == 0)      { Hin = Hout * 2; Win = Wout * 2; iy0 = sy * 16 * MF - 1; ix0 = sx * 16 - 1; }
    else if (MODE == 1) { Hin = Hout;     Win = Wout;     iy0 = sy * 8 * MF - 1;  ix0 = sx * 8 - 1; }
    else                { Hin = Hout / 2; Win = Wout / 2; iy0 = sy * 8 * MF;      ix0 = sx * 8; }

    // ldmatrix per-lane row address (patch-space pixel + k-half), fragment 0
    const int lr   = lane & 7;
    const int sel  = lane >> 3;
    const int row8 = sel & 1;
    const int kh2  = sel >> 1;
    int pix;
    if (MODE == 0) pix = (4 * wm + 2 * row8) * PW + lr;      // even-plane idx lr (col 2*lr)
    else           pix = (2 * wm + row8) * PW + lr;
    const uint32_t smem_a = (uint32_t)__cvta_generic_to_shared(smem);
    const uint32_t offb   = (uint32_t)((pix * CSTR + kh2 * 8) * 2);

    float acc[NACC][4][4];
#pragma unroll
    for (int m = 0; m < NACC; m++)
#pragma unroll
        for (int i = 0; i < 4; i++)
#pragma unroll
            for (int j = 0; j < 4; j++) acc[m][i][j] = 0.f;

    const int nch = Ci >> 4;
    const __half* inHiN = inHi + (size_t)n * Hin * Win * Ci;
    const __half* inLoN = inLo + (size_t)n * Hin * Win * Ci;

    int ciB = 0, nci = Ci;
    if (SPLIT > 1) { nci = Ci / SPLIT; ciB = split * nci; }
    const int nchunks = nci >> 4;

    // ---- staging (weights + patch for chunk cidx into buffer bsel) ----
    auto stage = [&](int cidx, int bsel) {
        const int ci0 = ciB + (cidx << 4);
        const int ch  = ci0 >> 4;
        const uint32_t base = smem_a + bsel * BUFSZ;
#pragma unroll 1
        for (int j = tid; j < 9 * 256; j += 256) {
            int t = j >> 8;
            int r = j & 255;
            const uint4* src = &w4[((size_t)(t * nch + ch) * 4 + (r >> 6)) * Co + cob + (r & 63)];
            cp16(base + WOFF + j * 16, src, 16);
        }
#pragma unroll 1
        for (int s = tid; s < NPX; s += 256) {
            int r = s / PW, c = s - r * PW;
            int iy = iy0 + r, ix = ix0 + c;
            bool ok = ((unsigned)iy < (unsigned)Hin) && ((unsigned)ix < (unsigned)Win);
            size_t gix = ((size_t)iy * Win + ix) * Ci + ci0;
            const __half* ph = ok ? (inHiN + gix) : inHiN;
            const __half* pl = ok ? (inLoN + gix) : inLoN;
            int sz = ok ? 16 : 0;
            // MODE 0: even/odd column-plane remap for conflict-free A ldmatrix
            int sdst = (MODE == 0) ? (r * PW + ((c & 1) ? 9 + (c >> 1) : (c >> 1))) : s;
            uint32_t dh = base + sdst * (CSTR * 2);
            uint32_t dl = base + PATB + sdst * (CSTR * 2);
            cp16(dh, ph, sz);      cp16(dh + 16, ph + 8, sz);
            cp16(dl, pl, sz);      cp16(dl + 16, pl + 8, sz);
        }
        cp_commit();
    };

    // ---- pipelined main loop ----
    stage(0, 0);
#pragma unroll 1
    for (int c = 0; c < nchunks; c++) {
        const int bsel = (DB == 2) ? (c & 1) : 0;
        if (DB == 2 && c + 1 < nchunks) {
            stage(c + 1, (c + 1) & 1);
            cp_wait_n<1>();
        } else {
            cp_wait_n<0>();
        }
        __syncthreads();

        const uint32_t bbase = smem_a + bsel * BUFSZ;
        const uint4*  wbuf  = (const uint4*)(smem + bsel * BUFSZ + WOFF);

        if (MODE == 2) {
            // merged-class: 4 A-offset groups, taps accumulate into their class
#pragma unroll
            for (int grp = 0; grp < 4; grp++) {
                const uint32_t ab = (uint32_t)(gtoff[grp] * CSTR * 2);
                uint32_t ah[4], al[4];
                ldsm4(ah[0], ah[1], ah[2], ah[3], bbase + offb + ab);
                ldsm4(al[0], al[1], al[2], al[3], bbase + PATB + offb + ab);
#pragma unroll
                for (int k = 0; k < gcnt[grp]; k++) {
                    constexpr int dummy = 0; (void)dummy;
                    const int t  = gtap[grp][k];
                    const int cl = clsOf[t];
                    const uint4* wrow = wbuf + (t << 8) + (tig << 6);
#pragma unroll
                    for (int sub = 0; sub < 4; sub++) {
                        uint4 bq = wrow[wn * 32 + sub * 8 + g];
                        mma16816(acc[cl][sub], ah[0], ah[1], ah[2], ah[3], bq.x, bq.y);
                        mma16816(acc[cl][sub], ah[0], ah[1], ah[2], ah[3], bq.z, bq.w);
                        mma16816(acc[cl][sub], al[0], al[1], al[2], al[3], bq.x, bq.y);
                    }
                }
            }
        } else {
#pragma unroll
            for (int t = 0; t < 9; t++) {
                uint32_t ab;
                if (MODE == 0) {
                    const int kh = t / 3, kw = t % 3;
                    ab = (uint32_t)((kh * PW + (kw == 0 ? 0 : (kw == 1 ? 9 : 1))) * CSTR * 2);
                } else {
                    ab = (uint32_t)(((t / 3) * PW + (t % 3)) * CSTR * 2);
                }
                uint32_t ah[MF][4], al[MF][4];
#pragma unroll
                for (int m = 0; m < MF; m++) {
                    ldsm4(ah[m][0], ah[m][1], ah[m][2], ah[m][3], bbase + offb + ab + m * MDEL);
                    ldsm4(al[m][0], al[m][1], al[m][2], al[m][3], bbase + PATB + offb + ab + m * MDEL);
                }
                const uint4* wrow = wbuf + (t << 8) + (tig << 6);
#pragma unroll
                for (int sub = 0; sub < 4; sub++) {
                    uint4 bq = wrow[wn * 32 + sub * 8 + g];
#pragma unroll
                    for (int m = 0; m < MF; m++) {
                        mma16816(acc[m][sub], ah[m][0], ah[m][1], ah[m][2], ah[m][3], bq.x, bq.y);
                        mma16816(acc[m][sub], ah[m][0], ah[m][1], ah[m][2], ah[m][3], bq.z, bq.w);
                        mma16816(acc[m][sub], al[m][0], al[m][1], al[m][2], al[m][3], bq.x, bq.y);
                    }
                }
            }
        }
        __syncthreads();
        if (DB == 1 && c + 1 < nchunks) stage(c + 1, 0);
    }

    // ---- epilogue ----
    const int colb = cob + wn * 32 + 2 * tig;
#pragma unroll
    for (int m = 0; m < NACC; m++) {
        int ohA, ohB, ow;
        if (MODE == 2) {
            // m = class index; quad row = sy*8 + 2*wm (+1 for c2c3)
            int pr = m >> 1, pc = m & 1;
            ohA = (sy * 8 + 2 * wm) * 2 + pr;
            ohB = ohA + 2;
            ow  = (sx * 8 + g) * 2 + pc;
        } else {
            ohA = sy * 8 * MF + 2 * wm + 8 * m;
            ohB = ohA + 1;
            ow  = sx * 8 + g;
        }
        if (SPLIT == 1) {
#pragma unroll
            for (int sub = 0; sub < 4; sub++) {
                int col = colb + sub * 8;
                float b0 = __ldg(&bias[col]), b1 = __ldg(&bias[col + 1]);
                float v0 = acc[m][sub][0] + b0, v1 = acc[m][sub][1] + b1;
                float v2 = acc[m][sub][2] + b0, v3 = acc[m][sub][3] + b1;
                if (act) { v0 = lrelu(v0); v1 = lrelu(v1); v2 = lrelu(v2); v3 = lrelu(v3); }
                __half h0, h1, h2, h3, l0, l1, l2, l3;
                split16(v0, h0, l0); split16(v1, h1, l1);
                split16(v2, h2, l2); split16(v3, h3, l3);
                size_t iA = (((size_t)n * Hout + ohA) * Wout + ow) * Co + col;
                size_t iB = (((size_t)n * Hout + ohB) * Wout + ow) * Co + col;
                *(__half2*)(outHi + iA) = __halves2half2(h0, h1);
                *(__half2*)(outHi + iB) = __halves2half2(h2, h3);
                *(__half2*)(outLo + iA) = __halves2half2(l0, l1);
                *(__half2*)(outLo + iB) = __halves2half2(l2, l3);
            }
        } else {
            float* po = outP + (size_t)split * ((size_t)NB * Hout * Wout * Co);
#pragma unroll
            for (int sub = 0; sub < 4; sub++) {
                int col = colb + sub * 8;
                float2* pA = (float2*)(po + (((size_t)n * Hout + ohA) * Wout + ow) * Co + col);
                float2* pB = (float2*)(po + (((size_t)n * Hout + ohB) * Wout + ow) * Co + col);
                *pA = make_float2(acc[m][sub][0], acc[m][sub][1]);
                *pB = make_float2(acc[m][sub][2], acc[m][sub][3]);
            }
        }
    }
}

// ---------------------------------------------------------------------------
// Fused weight repack for ALL layers in ONE launch.
// w [Co][Ci][3][3] -> fused B-fragment uint4 (hi pair, hi pair, lo pair, lo pair)
// ---------------------------------------------------------------------------
struct WPtrs { const float* p[11]; };

__global__ void repack_all(WPtrs wp, uint4* __restrict__ out, int total)
{
    int j = blockIdx.x * 256 + threadIdx.x;
    if (j >= total) return;
    int L = 0;
#pragma unroll
    for (int i = 1; i < 11; i++) if (j >= rk_offs[i]) L = i;
    int jj = j - rk_offs[L];
    int Ci = rk_ci[L], Cip = rk_cip[L], Co = rk_co[L];
    const float* w = wp.p[L];

    int co = jj % Co;
    int r  = jj / Co;
    int k4 = r & 3; r >>= 2;
    int nch = Cip >> 4;
    int ch  = r % nch;
    int t   = r / nch;
    int cbase = ch * 16 + 2 * k4;
    int cs[4] = {cbase, cbase + 1, cbase + 8, cbase + 9};
    __half h[4], l[4];
#pragma unroll
    for (int e = 0; e < 4; e++) {
        float v = (cs[e] < Ci) ? w[((size_t)co * Ci + cs[e]) * 9 + t] : 0.f;
        split16(v, h[e], l[e]);
    }
    uint4 o;
    o.x = (uint32_t)__half_as_ushort(h[0]) | ((uint32_t)__half_as_ushort(h[1]) << 16);
    o.y = (uint32_t)__half_as_ushort(h[2]) | ((uint32_t)__half_as_ushort(h[3]) << 16);
    o.z = (uint32_t)__half_as_ushort(l[0]) | ((uint32_t)__half_as_ushort(l[1]) << 16);
    o.w = (uint32_t)__half_as_ushort(l[2]) | ((uint32_t)__half_as_ushort(l[3]) << 16);
    out[j] = o;
}

// ---------------------------------------------------------------------------
// input transpose NCHW -> NHWC hi/lo planes, C=3 padded to 16
// ---------------------------------------------------------------------------
__global__ void to_planes(const float* __restrict__ x, __half* __restrict__ Xhi,
                          __half* __restrict__ Xlo)
{
    int i = blockIdx.x * 256 + threadIdx.x;
    if (i >= 2 * 512 * 512) return;
    int n = i >> 18;
    int p = i & 262143;
    union { __half h[16]; uint4 u[2]; } H, L;
#pragma unroll
    for (int e = 0; e < 16; e++) { H.h[e] = __ushort_as_half(0); L.h[e] = __ushort_as_half(0); }
#pragma unroll
    for (int c = 0; c < 3; c++) {
        float v = x[((size_t)n * 3 + c) * 262144 + p];
        split16(v, H.h[c], L.h[c]);
    }
    ((uint4*)Xhi)[(size_t)i * 2]     = H.u[0];
    ((uint4*)Xhi)[(size_t)i * 2 + 1] = H.u[1];
    ((uint4*)Xlo)[(size_t)i * 2]     = L.u[0];
    ((uint4*)Xlo)[(size_t)i * 2 + 1] = L.u[1];
}

// ---------------------------------------------------------------------------
// split-K reduces
// ---------------------------------------------------------------------------
__global__ void reduce_k_f16(const float* __restrict__ part, const float* __restrict__ bias,
                             __half* __restrict__ oh, __half* __restrict__ ol,
                             int S, int per, int Co, int act)
{
    int i = blockIdx.x * 256 + threadIdx.x;
    if (i >= per) return;
    float s = 0.f;
    for (int k = 0; k < S; k++) s += part[(size_t)k * per + i];
    float v = s + __ldg(&bias[i % Co]);
    if (act) v = lrelu(v);
    __half h, l;
    split16(v, h, l);
    oh[i] = h;
    ol[i] = l;
}

__global__ void reduce_k_f32(const float* __restrict__ part, const float* __restrict__ bias,
                             float* __restrict__ out, int S, int per, int Co)
{
    int i = blockIdx.x * 256 + threadIdx.x;
    if (i >= per) return;
    float s = 0.f;
    for (int k = 0; k < S; k++) s += part[(size_t)k * per + i];
    out[i] = s + __ldg(&bias[i % Co]);
}

// ---------------------------------------------------------------------------
// BatchNorm (batch stats) on fp32 NHWC, apply -> hi/lo planes
// ---------------------------------------------------------------------------
__global__ void bn_stats(const float* __restrict__ x, int rows, int C)
{
    int c = blockIdx.x * 256 + threadIdx.x;
    if (c >= C) return;
    float s = 0.f, s2 = 0.f;
    for (int r = 0; r < rows; r++) {
        float v = x[(size_t)r * C + c];
        s += v;
        s2 += v * v;
    }
    float m   = s / rows;
    float var = s2 / rows - m * m;
    g_mean[c] = m;
    g_rstd[c] = rsqrtf(var + 1e-5f);
}

__global__ void bn_apply_f16(const float* __restrict__ x, const float* __restrict__ gamma,
                             const float* __restrict__ beta, __half* __restrict__ oh,
                             __half* __restrict__ ol, int C, int total)
{
    int i = blockIdx.x * 256 + threadIdx.x;
    if (i >= total) return;
    int c = i % C;
    float v = (x[i] - g_mean[c]) * g_rstd[c] * __ldg(&gamma[c]) + __ldg(&beta[c]);
    v = lrelu(v);
    __half h, l;
    split16(v, h, l);
    oh[i] = h;
    ol[i] = l;
}

// ---------------------------------------------------------------------------
// Epilogue: 1x1 conv 64->3, hi/lo planes in -> NCHW fp32 out
// ---------------------------------------------------------------------------
__global__ void ep_nhwc(const __half* __restrict__ ih, const __half* __restrict__ il,
                        const float* __restrict__ w, const float* __restrict__ b,
                        float* __restrict__ out)
{
    int i = blockIdx.x * 256 + threadIdx.x;
    if (i >= 2 * 512 * 512) return;
    const __half* ph = ih + (size_t)i * 64;
    const __half* pl = il + (size_t)i * 64;
    float a0 = __ldg(&b[0]), a1 = __ldg(&b[1]), a2 = __ldg(&b[2]);
#pragma unroll
    for (int c = 0; c < 64; c++) {
        float v = __half2float(ph[c]) + __half2float(pl[c]);
        a0 += v * __ldg(&w[c]);
        a1 += v * __ldg(&w[64 + c]);
        a2 += v * __ldg(&w[128 + c]);
    }
    int n = i >> 18;
    int p = i & 262143;
    out[((size_t)n * 3 + 0) * 262144 + p] = a0;
    out[((size_t)n * 3 + 1) * 262144 + p] = a1;
    out[((size_t)n * 3 + 2) * 262144 + p] = a2;
}

// ---------------------------------------------------------------------------
// Launch sequence
// ---------------------------------------------------------------------------
// per-buffer sizes: patches(hi+lo) + weights (all modes stage 9 taps now)
static const int BUF_M0 = (33 * 17) * 24 * 2 * 2 + 9 * 256 * 16;   // 90720
static const int BUF_M1 = (18 * 10) * 24 * 2 * 2 + 9 * 256 * 16;   // 54144
static const int BUF_M2 = (9 * 9)   * 24 * 2 * 2 + 9 * 256 * 16;   // 44640 (merged, MF=1)

extern "C" void kernel_launch(void* const* d_in, const int* in_sizes, int n_in,
                              void* d_out, int out_size)
{
    (void)in_sizes; (void)n_in; (void)out_size;
    const float* x     = (const float*)d_in[0];
    const float* wd[5] = {(const float*)d_in[1], (const float*)d_in[3], (const float*)d_in[5],
                          (const float*)d_in[7], (const float*)d_in[9]};
    const float* bd[5] = {(const float*)d_in[2], (const float*)d_in[4], (const float*)d_in[6],
                          (const float*)d_in[8], (const float*)d_in[10]};
    const float* w_in  = (const float*)d_in[11];
    const float* b_in  = (const float*)d_in[12];
    const float* gamma = (const float*)d_in[13];
    const float* beta  = (const float*)d_in[14];
    const float* wu[5] = {(const float*)d_in[15], (const float*)d_in[17], (const float*)d_in[19],
                          (const float*)d_in[21], (const float*)d_in[23]};
    const float* bu[5] = {(const float*)d_in[16], (const float*)d_in[18], (const float*)d_in[20],
                          (const float*)d_in[22], (const float*)d_in[24]};
    const float* wep = (const float*)d_in[25];
    const float* bep = (const float*)d_in[26];
    float* outp = (float*)d_out;

    float *A, *B, *P, *C, *X;
    uint4* W4;
    cudaGetSymbolAddress((void**)&A, g_bufA);
    cudaGetSymbolAddress((void**)&B, g_bufB);
    cudaGetSymbolAddress((void**)&P, g_bufP);
    cudaGetSymbolAddress((void**)&C, g_bufC);
    cudaGetSymbolAddress((void**)&X, g_bufX);
    cudaGetSymbolAddress((void**)&W4, g_w4);

    __half* Ahi = (__half*)A;  __half* Alo = Ahi + 33554432;
    __half* Bhi = (__half*)B;  __half* Blo = Bhi + 33554432;
    __half* Xhi = (__half*)X;  __half* Xlo = Xhi + 8388608;

    cudaFuncSetAttribute(conv_tc<0, 1, 2, 1>, cudaFuncAttributeMaxDynamicSharedMemorySize, BUF_M0);
    cudaFuncSetAttribute(conv_tc<0, 2, 2, 1>, cudaFuncAttributeMaxDynamicSharedMemorySize, BUF_M0);
    cudaFuncSetAttribute(conv_tc<0, 4, 2, 1>, cudaFuncAttributeMaxDynamicSharedMemorySize, BUF_M0);
    cudaFuncSetAttribute(conv_tc<1, 4, 2, 2>, cudaFuncAttributeMaxDynamicSharedMemorySize, 2 * BUF_M1);
    cudaFuncSetAttribute(conv_tc<2, 1, 1, 2>, cudaFuncAttributeMaxDynamicSharedMemorySize, 2 * BUF_M2);
    cudaFuncSetAttribute(conv_tc<2, 2, 1, 2>, cudaFuncAttributeMaxDynamicSharedMemorySize, 2 * BUF_M2);
    cudaFuncSetAttribute(conv_tc<2, 4, 1, 2>, cudaFuncAttributeMaxDynamicSharedMemorySize, 2 * BUF_M2);

    // layer weight offsets (must match rk_offs): 9*(Cip/16)*4*Co
    const int Lcip[11] = {16, 64, 128, 256, 512, 1024, 1024, 512, 256, 128, 64};
    const int Lco[11]  = {64, 128, 256, 512, 1024, 1024, 512, 256, 128, 64, 64};
    size_t off[12];
    off[0] = 0;
    for (int i = 0; i < 11; i++) off[i + 1] = off[i] + (size_t)9 * (Lcip[i] / 16) * 4 * Lco[i];
    int total = (int)off[11];

    // ---- fused weight repack (one launch) + input planes ----
    WPtrs wp;
    wp.p[0] = wd[0]; wp.p[1] = wd[1]; wp.p[2] = wd[2]; wp.p[3] = wd[3]; wp.p[4] = wd[4];
    wp.p[5] = w_in;
    wp.p[6] = wu[0]; wp.p[7] = wu[1]; wp.p[8] = wu[2]; wp.p[9] = wu[3]; wp.p[10] = wu[4];
    repack_all<<<(total + 255) / 256, 256>>>(wp, W4, total);
    to_planes<<<(524288 + 255) / 256, 256>>>(x, Xhi, Xlo);

    // ---- encoder (MODE 0: DB=1, 2 CTAs/SM) ----
    conv_tc<0, 1, 2, 1><<<dim3(32, 16, 2), 256, BUF_M0>>>(Xhi, Xlo, W4 + off[0], bd[0], Ahi, Alo, nullptr, 2, 16, 64, 256, 256, 1);
    conv_tc<0, 1, 2, 1><<<dim3(16, 8, 4), 256, BUF_M0>>>(Ahi, Alo, W4 + off[1], bd[1], Bhi, Blo, nullptr, 2, 64, 128, 128, 128, 1);
    conv_tc<0, 1, 2, 1><<<dim3(8, 4, 8), 256, BUF_M0>>>(Bhi, Blo, W4 + off[2], bd[2], Ahi, Alo, nullptr, 2, 128, 256, 64, 64, 1);
    conv_tc<0, 2, 2, 1><<<dim3(8, 2, 16), 256, BUF_M0>>>(Ahi, Alo, W4 + off[3], nullptr, nullptr, nullptr, P, 2, 256, 512, 32, 32, 0);
    reduce_k_f16<<<(1048576 + 255) / 256, 256>>>(P, bd[3], Bhi, Blo, 2, 1048576, 512, 1);
    conv_tc<0, 4, 2, 1><<<dim3(8, 1, 32), 256, BUF_M0>>>(Bhi, Blo, W4 + off[4], nullptr, nullptr, nullptr, P, 2, 512, 1024, 16, 16, 0);
    reduce_k_f16<<<(524288 + 255) / 256, 256>>>(P, bd[4], Ahi, Alo, 4, 524288, 1024, 1);

    // ---- inner conv + BN + LReLU ----
    conv_tc<1, 4, 2, 2><<<dim3(8, 1, 32), 256, 2 * BUF_M1>>>(Ahi, Alo, W4 + off[5], nullptr, nullptr, nullptr, P, 2, 1024, 1024, 16, 16, 0);
    reduce_k_f32<<<(524288 + 255) / 256, 256>>>(P, b_in, C, 4, 524288, 1024);
    bn_stats<<<4, 256>>>(C, 512, 1024);
    bn_apply_f16<<<(524288 + 255) / 256, 256>>>(C, gamma, beta, Bhi, Blo, 1024, 524288);

    // ---- decoder (merged-class MODE 2, MF=1) ----
    // u0: 1024->512, out 32x32: SX=2, SY=2, z=2*8, SPLIT=4
    conv_tc<2, 4, 1, 2><<<dim3(8, 2, 16), 256, 2 * BUF_M2>>>(Bhi, Blo, W4 + off[6], nullptr, nullptr, nullptr, P, 2, 1024, 512, 32, 32, 0);
    reduce_k_f16<<<(1048576 + 255) / 256, 256>>>(P, bu[0], Ahi, Alo, 4, 1048576, 512, 1);
    // u1: 512->256, out 64x64: SX=4, SY=4, z=2*4, SPLIT=2
    conv_tc<2, 2, 1, 2><<<dim3(8, 4, 8), 256, 2 * BUF_M2>>>(Ahi, Alo, W4 + off[7], nullptr, nullptr, nullptr, P, 2, 512, 256, 64, 64, 0);
    reduce_k_f16<<<(2097152 + 255) / 256, 256>>>(P, bu[1], Bhi, Blo, 2, 2097152, 256, 1);
    // u2: 256->128, out 128x128: SX=8, SY=8, z=2*2
    conv_tc<2, 1, 1, 2><<<dim3(8, 8, 4), 256, 2 * BUF_M2>>>(Bhi, Blo, W4 + off[8], bu[2], Ahi, Alo, nullptr, 2, 256, 128, 128, 128, 1);
    // u3: 128->64, out 256x256: SX=16, SY=16, z=2
    conv_tc<2, 1, 1, 2><<<dim3(16, 16, 2), 256, 2 * BUF_M2>>>(Ahi, Alo, W4 + off[9], bu[3], Bhi, Blo, nullptr, 2, 128, 64, 256, 256, 1);
    // u4: 64->64, out 512x512: SX=32, SY=32, z=2
    conv_tc<2, 1, 1, 2><<<dim3(32, 32, 2), 256, 2 * BUF_M2>>>(Bhi, Blo, W4 + off[10], bu[4], Ahi, Alo, nullptr, 2, 64, 64, 512, 512, 1);

    // ---- epilogue 1x1 ----
    ep_nhwc<<<(524288 + 255) / 256, 256>>>(Ahi, Alo, wep, bep, outp);
}

// round 14
// speedup vs baseline: 1.6500x; 1.6500x over previous
#include <cuda_runtime.h>
#include <cuda_fp16.h>
#include <cstdint>

// ---------------------------------------------------------------------------
// Scratch (static __device__ globals; no allocation allowed)
// ---------------------------------------------------------------------------
__device__ float    g_bufA[33554432];   // ping: fp16 hi/lo planes (as halves)
__device__ float    g_bufB[33554432];   // pong
__device__ float    g_bufP[16777216];   // split-K fp32 partials
__device__ float    g_bufC[1048576];    // fp32 inner activations (BN input)
__device__ float    g_bufX[8388608];    // input hi/lo planes, C padded to 16
__device__ uint4    g_w4[5504256];      // fused B-fragment weights (hi,hi,lo,lo)
__device__ float    g_mean[1024];
__device__ float    g_rstd[1024];

// decoder parity-class tap tables (mode 2, PW = 9)
__constant__ int c_tcnt[4]    = {1, 2, 2, 4};
__constant__ int c_twid[4][4] = {{4,0,0,0},{3,5,0,0},{1,7,0,0},{0,2,6,8}};
__constant__ int c_toff[4][4] = {{0,0,0,0},{0,1,0,0},{0,9,0,0},{0,1,9,10}};

// fused-repack layer tables (element = one uint4 = 4 weights hi+lo)
__constant__ int rk_ci[11]  = {3, 64, 128, 256, 512, 1024, 1024, 512, 256, 128, 64};
__constant__ int rk_cip[11] = {16, 64, 128, 256, 512, 1024, 1024, 512, 256, 128, 64};
__constant__ int rk_co[11]  = {64, 128, 256, 512, 1024, 1024, 512, 256, 128, 64, 64};
// offsets: cumulative 9*(Cip/16)*4*Co per layer (VERIFIED against host off[])
__constant__ int rk_offs[12] = {0, 2304, 20736, 94464, 389376, 1569024, 3928320,
                                5107968, 5402880, 5476608, 5495040, 5504256};

__device__ __forceinline__ float lrelu(float v) { return v >= 0.f ? v : 0.01f * v; }

__device__ __forceinline__ void cp16(uint32_t dst, const void* src, int sz)
{
    asm volatile("cp.async.cg.shared.global [%0], [%1], 16, %2;"
                 :: "r"(dst), "l"(src), "r"(sz));
}
__device__ __forceinline__ void cp_commit()
{
    asm volatile("cp.async.commit_group;");
}
template <int N>
__device__ __forceinline__ void cp_wait_n()
{
    asm volatile("cp.async.wait_group %0;" :: "n"(N));
}

__device__ __forceinline__ void ldsm4(uint32_t& r0, uint32_t& r1, uint32_t& r2,
                                      uint32_t& r3, uint32_t addr)
{
    asm volatile("ldmatrix.sync.aligned.m8n8.x4.shared.b16 {%0,%1,%2,%3}, [%4];"
                 : "=r"(r0), "=r"(r1), "=r"(r2), "=r"(r3) : "r"(addr));
}

__device__ __forceinline__ void mma16816(float* acc, uint32_t a0, uint32_t a1,
                                         uint32_t a2, uint32_t a3, uint32_t b0, uint32_t b1)
{
    asm volatile("mma.sync.aligned.m16n8k16.row.col.f32.f16.f16.f32 "
                 "{%0,%1,%2,%3},{%4,%5,%6,%7},{%8,%9},{%0,%1,%2,%3};"
                 : "+f"(acc[0]), "+f"(acc[1]), "+f"(acc[2]), "+f"(acc[3])
                 : "r"(a0), "r"(a1), "r"(a2), "r"(a3), "r"(b0), "r"(b1));
}

__device__ __forceinline__ void split16(float v, __half& h, __half& l)
{
    h = __float2half_rn(v);
    l = __float2half_rn(v - __half2float(h));
}

// ---------------------------------------------------------------------------
// Tensor-core implicit-GEMM conv (NHWC fp16 hi/lo planes), 3-term fp16 split.
// MF = M-fragments per warp (tile M = 64*MF pixels). N tile = 64 co.
// DB = staging buffers (2 = cp.async double-buffered, 1 = single buffer).
// MODE 0: SAME conv + stride-2 subsample. Patch stored in EVEN/ODD column
//         planes (pixel (r,c) at r*PW + (c even ? c/2 : 9+(c-1)/2)) so the
//         stride-2 A-fragment reads are 48B apart -> conflict-free ldmatrix.
// MODE 1: SAME conv stride 1
// MODE 2: zero-insert up2 + SAME conv, one parity class per block
// Block: 256 thr = 8 warps (4 M x 2 N). K-chunk 16 channels.
// ---------------------------------------------------------------------------
template <int MODE, int SPLIT, int MF, int DB>
__global__ void __launch_bounds__(256) conv_tc(
    const __half* __restrict__ inHi, const __half* __restrict__ inLo,
    const uint4* __restrict__ w4, const float* __restrict__ bias,
    __half* __restrict__ outHi, __half* __restrict__ outLo,
    float* __restrict__ outP,
    int NB, int Ci, int Co, int Hout, int Wout, int act)
{
    constexpr int PW   = (MODE == 0) ? 17 : ((MODE == 1) ? 10 : 9);
    constexpr int PH   = (MODE == 0) ? (16 * MF + 1) : ((MODE == 1) ? (8 * MF + 2) : (8 * MF + 1));
    constexpr int NPX  = PH * PW;
    constexpr int CSTR = 24;                       // halves per pixel row (16 used)
    constexpr int MAXT = (MODE == 2) ? 4 : 9;
    constexpr int MDEL = ((MODE == 0) ? 16 : 8) * PW * CSTR * 2;  // byte delta between M-fragments
    constexpr int PATB = NPX * CSTR * 2;           // one plane bytes
    constexpr int WOFF = 2 * PATB;                 // weights offset inside buffer
    constexpr int BUFSZ = WOFF + MAXT * 256 * 16;  // one staging buffer bytes

    extern __shared__ __align__(16) char smem[];

    const int tid  = threadIdx.x;
    const int lane = tid & 31, w = tid >> 5;
    const int g    = lane >> 2, tig = lane & 3;
    const int wm   = w & 3, wn = w >> 2;

    const int SX    = (MODE == 2) ? (Wout >> 4) : (Wout >> 3);
    const int sx    = blockIdx.x % SX;
    const int split = blockIdx.x / SX;
    const int sy    = blockIdx.y;
    const int gpc   = Co >> 6;
    int z = blockIdx.z;
    int cls = 0;
    if (MODE == 2) { cls = z / (NB * gpc); z -= cls * (NB * gpc); }
    const int n   = z / gpc;
    const int cob = (z - n * gpc) << 6;

    const int T = (MODE == 2) ? c_tcnt[cls] : 9;

    int Hin, Win, iy0, ix0;
    if (MODE == 0)      { Hin = Hout * 2; Win = Wout * 2; iy0 = sy * 16 * MF - 1; ix0 = sx * 16 - 1; }
    else if (MODE == 1) { Hin = Hout;     Win = Wout;     iy0 = sy * 8 * MF - 1;  ix0 = sx * 8 - 1; }
    else                { Hin = Hout / 2; Win = Wout / 2; iy0 = sy * 8 * MF;      ix0 = sx * 8; }

    // ldmatrix per-lane row address (patch-space pixel + k-half), fragment 0
    const int lr   = lane & 7;
    const int sel  = lane >> 3;
    const int row8 = sel & 1;
    const int kh2  = sel >> 1;
    int pix;
    if (MODE == 0) pix = (4 * wm + 2 * row8) * PW + lr;      // even-plane idx lr (col 2*lr)
    else           pix = (2 * wm + row8) * PW + lr;
    const uint32_t smem_a = (uint32_t)__cvta_generic_to_shared(smem);
    const uint32_t offb   = (uint32_t)((pix * CSTR + kh2 * 8) * 2);

    float acc[MF][4][4];
#pragma unroll
    for (int m = 0; m < MF; m++)
#pragma unroll
        for (int i = 0; i < 4; i++)
#pragma unroll
            for (int j = 0; j < 4; j++) acc[m][i][j] = 0.f;

    const int nch = Ci >> 4;
    const __half* inHiN = inHi + (size_t)n * Hin * Win * Ci;
    const __half* inLoN = inLo + (size_t)n * Hin * Win * Ci;

    int ciB = 0, nci = Ci;
    if (SPLIT > 1) { nci = Ci / SPLIT; ciB = split * nci; }
    const int nchunks = nci >> 4;

    // ---- staging (weights + patch for chunk cidx into buffer bsel) ----
    auto stage = [&](int cidx, int bsel) {
        const int ci0 = ciB + (cidx << 4);
        const int ch  = ci0 >> 4;
        const uint32_t base = smem_a + bsel * BUFSZ;
#pragma unroll 1
        for (int j = tid; j < T * 256; j += 256) {
            int t  = j >> 8;
            int r  = j & 255;
            int w9 = (MODE == 2) ? c_twid[cls][t] : t;
            const uint4* src = &w4[((size_t)(w9 * nch + ch) * 4 + (r >> 6)) * Co + cob + (r & 63)];
            cp16(base + WOFF + j * 16, src, 16);
        }
#pragma unroll 1
        for (int s = tid; s < NPX; s += 256) {
            int r = s / PW, c = s - r * PW;
            int iy = iy0 + r, ix = ix0 + c;
            bool ok = ((unsigned)iy < (unsigned)Hin) && ((unsigned)ix < (unsigned)Win);
            size_t gix = ((size_t)iy * Win + ix) * Ci + ci0;
            const __half* ph = ok ? (inHiN + gix) : inHiN;
            const __half* pl = ok ? (inLoN + gix) : inLoN;
            int sz = ok ? 16 : 0;
            // MODE 0: even/odd column-plane remap for conflict-free A ldmatrix
            int sdst = (MODE == 0) ? (r * PW + ((c & 1) ? 9 + (c >> 1) : (c >> 1))) : s;
            uint32_t dh = base + sdst * (CSTR * 2);
            uint32_t dl = base + PATB + sdst * (CSTR * 2);
            cp16(dh, ph, sz);      cp16(dh + 16, ph + 8, sz);
            cp16(dl, pl, sz);      cp16(dl + 16, pl + 8, sz);
        }
        cp_commit();
    };

    // ---- pipelined main loop ----
    stage(0, 0);
#pragma unroll 1
    for (int c = 0; c < nchunks; c++) {
        const int bsel = (DB == 2) ? (c & 1) : 0;
        if (DB == 2 && c + 1 < nchunks) {
            stage(c + 1, (c + 1) & 1);
            cp_wait_n<1>();
        } else {
            cp_wait_n<0>();
        }
        __syncthreads();

        const uint32_t bbase = smem_a + bsel * BUFSZ;
        const uint4*  wbuf  = (const uint4*)(smem + bsel * BUFSZ + WOFF);

#pragma unroll
        for (int t = 0; t < MAXT; t++) {
            if (MODE == 2 && t >= T) break;
            uint32_t ab;
            if (MODE == 0) {
                // even/odd plane tap offsets: kw=0 -> even idx g (+0);
                // kw=1 -> odd plane (+9*CSTR); kw=2 -> even idx g+1 (+CSTR)
                const int kh = t / 3, kw = t % 3;
                ab = (uint32_t)((kh * PW + (kw == 0 ? 0 : (kw == 1 ? 9 : 1))) * CSTR * 2);
            } else {
                const int toff = (MODE == 2) ? c_toff[cls][t] : ((t / 3) * PW + (t % 3));
                ab = (uint32_t)(toff * CSTR * 2);
            }
            uint32_t ah[MF][4], al[MF][4];
#pragma unroll
            for (int m = 0; m < MF; m++) {
                ldsm4(ah[m][0], ah[m][1], ah[m][2], ah[m][3], bbase + offb + ab + m * MDEL);
                ldsm4(al[m][0], al[m][1], al[m][2], al[m][3], bbase + PATB + offb + ab + m * MDEL);
            }
            const uint4* wrow = wbuf + (t << 8) + (tig << 6);
#pragma unroll
            for (int sub = 0; sub < 4; sub++) {
                uint4 bq = wrow[wn * 32 + sub * 8 + g];
#pragma unroll
                for (int m = 0; m < MF; m++) {
                    mma16816(acc[m][sub], ah[m][0], ah[m][1], ah[m][2], ah[m][3], bq.x, bq.y);
                    mma16816(acc[m][sub], ah[m][0], ah[m][1], ah[m][2], ah[m][3], bq.z, bq.w);
                    mma16816(acc[m][sub], al[m][0], al[m][1], al[m][2], al[m][3], bq.x, bq.y);
                }
            }
        }
        __syncthreads();
        if (DB == 1 && c + 1 < nchunks) stage(c + 1, 0);
    }

    // ---- epilogue ----
    const int colb = cob + wn * 32 + 2 * tig;
#pragma unroll
    for (int m = 0; m < MF; m++) {
        int ohA, ohB, ow;
        if (MODE == 2) {
            int pr = cls >> 1, pc = cls & 1;
            int qr = sy * 8 * MF + 2 * wm + 8 * m;
            ohA = qr * 2 + pr;
            ohB = (qr + 1) * 2 + pr;
            ow  = (sx * 8 + g) * 2 + pc;
        } else {
            // block covers 8*MF OUTPUT rows in both MODE 0 and MODE 1
            ohA = sy * 8 * MF + 2 * wm + 8 * m;
            ohB = ohA + 1;
            ow  = sx * 8 + g;
        }
        if (SPLIT == 1) {
#pragma unroll
            for (int sub = 0; sub < 4; sub++) {
                int col = colb + sub * 8;
                float b0 = __ldg(&bias[col]), b1 = __ldg(&bias[col + 1]);
                float v0 = acc[m][sub][0] + b0, v1 = acc[m][sub][1] + b1;
                float v2 = acc[m][sub][2] + b0, v3 = acc[m][sub][3] + b1;
                if (act) { v0 = lrelu(v0); v1 = lrelu(v1); v2 = lrelu(v2); v3 = lrelu(v3); }
                __half h0, h1, h2, h3, l0, l1, l2, l3;
                split16(v0, h0, l0); split16(v1, h1, l1);
                split16(v2, h2, l2); split16(v3, h3, l3);
                size_t iA = (((size_t)n * Hout + ohA) * Wout + ow) * Co + col;
                size_t iB = (((size_t)n * Hout + ohB) * Wout + ow) * Co + col;
                *(__half2*)(outHi + iA) = __halves2half2(h0, h1);
                *(__half2*)(outHi + iB) = __halves2half2(h2, h3);
                *(__half2*)(outLo + iA) = __halves2half2(l0, l1);
                *(__half2*)(outLo + iB) = __halves2half2(l2, l3);
            }
        } else {
            float* po = outP + (size_t)split * ((size_t)NB * Hout * Wout * Co);
#pragma unroll
            for (int sub = 0; sub < 4; sub++) {
                int col = colb + sub * 8;
                float2* pA = (float2*)(po + (((size_t)n * Hout + ohA) * Wout + ow) * Co + col);
                float2* pB = (float2*)(po + (((size_t)n * Hout + ohB) * Wout + ow) * Co + col);
                *pA = make_float2(acc[m][sub][0], acc[m][sub][1]);
                *pB = make_float2(acc[m][sub][2], acc[m][sub][3]);
            }
        }
    }
}

// ---------------------------------------------------------------------------
// Fused weight repack for ALL layers in ONE launch.
// w [Co][Ci][3][3] -> fused B-fragment uint4 (hi pair, hi pair, lo pair, lo pair)
// ---------------------------------------------------------------------------
struct WPtrs { const float* p[11]; };

__global__ void repack_all(WPtrs wp, uint4* __restrict__ out, int total)
{
    int j = blockIdx.x * 256 + threadIdx.x;
    if (j >= total) return;
    int L = 0;
#pragma unroll
    for (int i = 1; i < 11; i++) if (j >= rk_offs[i]) L = i;
    int jj = j - rk_offs[L];
    int Ci = rk_ci[L], Cip = rk_cip[L], Co = rk_co[L];
    const float* w = wp.p[L];

    int co = jj % Co;
    int r  = jj / Co;
    int k4 = r & 3; r >>= 2;
    int nch = Cip >> 4;
    int ch  = r % nch;
    int t   = r / nch;
    int cbase = ch * 16 + 2 * k4;
    int cs[4] = {cbase, cbase + 1, cbase + 8, cbase + 9};
    __half h[4], l[4];
#pragma unroll
    for (int e = 0; e < 4; e++) {
        float v = (cs[e] < Ci) ? w[((size_t)co * Ci + cs[e]) * 9 + t] : 0.f;
        split16(v, h[e], l[e]);
    }
    uint4 o;
    o.x = (uint32_t)__half_as_ushort(h[0]) | ((uint32_t)__half_as_ushort(h[1]) << 16);
    o.y = (uint32_t)__half_as_ushort(h[2]) | ((uint32_t)__half_as_ushort(h[3]) << 16);
    o.z = (uint32_t)__half_as_ushort(l[0]) | ((uint32_t)__half_as_ushort(l[1]) << 16);
    o.w = (uint32_t)__half_as_ushort(l[2]) | ((uint32_t)__half_as_ushort(l[3]) << 16);
    out[j] = o;
}

// ---------------------------------------------------------------------------
// input transpose NCHW -> NHWC hi/lo planes, C=3 padded to 16
// ---------------------------------------------------------------------------
__global__ void to_planes(const float* __restrict__ x, __half* __restrict__ Xhi,
                          __half* __restrict__ Xlo)
{
    int i = blockIdx.x * 256 + threadIdx.x;
    if (i >= 2 * 512 * 512) return;
    int n = i >> 18;
    int p = i & 262143;
    union { __half h[16]; uint4 u[2]; } H, L;
#pragma unroll
    for (int e = 0; e < 16; e++) { H.h[e] = __ushort_as_half(0); L.h[e] = __ushort_as_half(0); }
#pragma unroll
    for (int c = 0; c < 3; c++) {
        float v = x[((size_t)n * 3 + c) * 262144 + p];
        split16(v, H.h[c], L.h[c]);
    }
    ((uint4*)Xhi)[(size_t)i * 2]     = H.u[0];
    ((uint4*)Xhi)[(size_t)i * 2 + 1] = H.u[1];
    ((uint4*)Xlo)[(size_t)i * 2]     = L.u[0];
    ((uint4*)Xlo)[(size_t)i * 2 + 1] = L.u[1];
}

// ---------------------------------------------------------------------------
// split-K reduces
// ---------------------------------------------------------------------------
__global__ void reduce_k_f16(const float* __restrict__ part, const float* __restrict__ bias,
                             __half* __restrict__ oh, __half* __restrict__ ol,
                             int S, int per, int Co, int act)
{
    int i = blockIdx.x * 256 + threadIdx.x;
    if (i >= per) return;
    float s = 0.f;
    for (int k = 0; k < S; k++) s += part[(size_t)k * per + i];
    float v = s + __ldg(&bias[i % Co]);
    if (act) v = lrelu(v);
    __half h, l;
    split16(v, h, l);
    oh[i] = h;
    ol[i] = l;
}

__global__ void reduce_k_f32(const float* __restrict__ part, const float* __restrict__ bias,
                             float* __restrict__ out, int S, int per, int Co)
{
    int i = blockIdx.x * 256 + threadIdx.x;
    if (i >= per) return;
    float s = 0.f;
    for (int k = 0; k < S; k++) s += part[(size_t)k * per + i];
    out[i] = s + __ldg(&bias[i % Co]);
}

// ---------------------------------------------------------------------------
// BatchNorm (batch stats) on fp32 NHWC, apply -> hi/lo planes
// ---------------------------------------------------------------------------
__global__ void bn_stats(const float* __restrict__ x, int rows, int C)
{
    int c = blockIdx.x * 256 + threadIdx.x;
    if (c >= C) return;
    float s = 0.f, s2 = 0.f;
    for (int r = 0; r < rows; r++) {
        float v = x[(size_t)r * C + c];
        s += v;
        s2 += v * v;
    }
    float m   = s / rows;
    float var = s2 / rows - m * m;
    g_mean[c] = m;
    g_rstd[c] = rsqrtf(var + 1e-5f);
}

__global__ void bn_apply_f16(const float* __restrict__ x, const float* __restrict__ gamma,
                             const float* __restrict__ beta, __half* __restrict__ oh,
                             __half* __restrict__ ol, int C, int total)
{
    int i = blockIdx.x * 256 + threadIdx.x;
    if (i >= total) return;
    int c = i % C;
    float v = (x[i] - g_mean[c]) * g_rstd[c] * __ldg(&gamma[c]) + __ldg(&beta[c]);
    v = lrelu(v);
    __half h, l;
    split16(v, h, l);
    oh[i] = h;
    ol[i] = l;
}

// ---------------------------------------------------------------------------
// Epilogue: 1x1 conv 64->3, hi/lo planes in -> NCHW fp32 out
// smem-staged: block handles 64 pixels; coalesced uint4 global loads;
// 4 threads/pixel (16ch each) + shfl reduce.
// ---------------------------------------------------------------------------
__global__ void __launch_bounds__(256) ep_nhwc(
    const __half* __restrict__ ih, const __half* __restrict__ il,
    const float* __restrict__ w, const float* __restrict__ b,
    float* __restrict__ out)
{
    __shared__ float  s_w[192];
    __shared__ __half s_h[64 * 72];   // 72-halves stride (bank spread)
    __shared__ __half s_l[64 * 72];

    const int tid = threadIdx.x;
    const size_t p0 = (size_t)blockIdx.x * 64;   // first pixel of this block

    if (tid < 192) s_w[tid] = w[tid];
    // coalesced copy: 64 px * 8 uint4 per plane
    const uint4* srcH = (const uint4*)(ih + p0 * 64);
    const uint4* srcL = (const uint4*)(il + p0 * 64);
#pragma unroll
    for (int j = tid; j < 512; j += 256) {
        int px = j >> 3, q = j & 7;
        *(uint4*)(s_h + px * 72 + q * 8) = srcH[j];
        *(uint4*)(s_l + px * 72 + q * 8) = srcL[j];
    }
    __syncthreads();

    const int px = tid >> 2;      // 0..63
    const int qt = tid & 3;       // 16-channel quarter
    const __half* ph = s_h + px * 72 + qt * 16;
    const __half* pl = s_l + px * 72 + qt * 16;
    float a0 = 0.f, a1 = 0.f, a2 = 0.f;
#pragma unroll
    for (int c = 0; c < 16; c++) {
        float v = __half2float(ph[c]) + __half2float(pl[c]);
        int cc = qt * 16 + c;
        a0 += v * s_w[cc];
        a1 += v * s_w[64 + cc];
        a2 += v * s_w[128 + cc];
    }
#pragma unroll
    for (int o = 1; o < 4; o <<= 1) {
        a0 += __shfl_xor_sync(0xffffffff, a0, o);
        a1 += __shfl_xor_sync(0xffffffff, a1, o);
        a2 += __shfl_xor_sync(0xffffffff, a2, o);
    }
    if (qt == 0) {
        size_t i = p0 + px;
        int n = (int)(i >> 18);
        int p = (int)(i & 262143);
        out[((size_t)n * 3 + 0) * 262144 + p] = a0 + __ldg(&b[0]);
        out[((size_t)n * 3 + 1) * 262144 + p] = a1 + __ldg(&b[1]);
        out[((size_t)n * 3 + 2) * 262144 + p] = a2 + __ldg(&b[2]);
    }
}

// ---------------------------------------------------------------------------
// Launch sequence
// ---------------------------------------------------------------------------
// per-buffer sizes: patches(hi+lo) + weights
static const int BUF_M0 = (33 * 17) * 24 * 2 * 2 + 9 * 256 * 16;   // 90720
static const int BUF_M1 = (18 * 10) * 24 * 2 * 2 + 9 * 256 * 16;   // 54144
static const int BUF_M2 = (17 * 9)  * 24 * 2 * 2 + 4 * 256 * 16;   // 31072

extern "C" void kernel_launch(void* const* d_in, const int* in_sizes, int n_in,
                              void* d_out, int out_size)
{
    (void)in_sizes; (void)n_in; (void)out_size;
    const float* x     = (const float*)d_in[0];
    const float* wd[5] = {(const float*)d_in[1], (const float*)d_in[3], (const float*)d_in[5],
                          (const float*)d_in[7], (const float*)d_in[9]};
    const float* bd[5] = {(const float*)d_in[2], (const float*)d_in[4], (const float*)d_in[6],
                          (const float*)d_in[8], (const float*)d_in[10]};
    const float* w_in  = (const float*)d_in[11];
    const float* b_in  = (const float*)d_in[12];
    const float* gamma = (const float*)d_in[13];
    const float* beta  = (const float*)d_in[14];
    const float* wu[5] = {(const float*)d_in[15], (const float*)d_in[17], (const float*)d_in[19],
                          (const float*)d_in[21], (const float*)d_in[23]};
    const float* bu[5] = {(const float*)d_in[16], (const float*)d_in[18], (const float*)d_in[20],
                          (const float*)d_in[22], (const float*)d_in[24]};
    const float* wep = (const float*)d_in[25];
    const float* bep = (const float*)d_in[26];
    float* outp = (float*)d_out;

    float *A, *B, *P, *C, *X;
    uint4* W4;
    cudaGetSymbolAddress((void**)&A, g_bufA);
    cudaGetSymbolAddress((void**)&B, g_bufB);
    cudaGetSymbolAddress((void**)&P, g_bufP);
    cudaGetSymbolAddress((void**)&C, g_bufC);
    cudaGetSymbolAddress((void**)&X, g_bufX);
    cudaGetSymbolAddress((void**)&W4, g_w4);

    __half* Ahi = (__half*)A;  __half* Alo = Ahi + 33554432;
    __half* Bhi = (__half*)B;  __half* Blo = Bhi + 33554432;
    __half* Xhi = (__half*)X;  __half* Xlo = Xhi + 8388608;

    cudaFuncSetAttribute(conv_tc<0, 1, 2, 1>, cudaFuncAttributeMaxDynamicSharedMemorySize, BUF_M0);
    cudaFuncSetAttribute(conv_tc<0, 2, 2, 1>, cudaFuncAttributeMaxDynamicSharedMemorySize, BUF_M0);
    cudaFuncSetAttribute(conv_tc<0, 4, 2, 1>, cudaFuncAttributeMaxDynamicSharedMemorySize, BUF_M0);
    cudaFuncSetAttribute(conv_tc<1, 4, 2, 2>, cudaFuncAttributeMaxDynamicSharedMemorySize, 2 * BUF_M1);
    cudaFuncSetAttribute(conv_tc<2, 1, 2, 2>, cudaFuncAttributeMaxDynamicSharedMemorySize, 2 * BUF_M2);
    cudaFuncSetAttribute(conv_tc<2, 4, 2, 2>, cudaFuncAttributeMaxDynamicSharedMemorySize, 2 * BUF_M2);

    // layer weight offsets (must match rk_offs): 9*(Cip/16)*4*Co
    const int Lcip[11] = {16, 64, 128, 256, 512, 1024, 1024, 512, 256, 128, 64};
    const int Lco[11]  = {64, 128, 256, 512, 1024, 1024, 512, 256, 128, 64, 64};
    size_t off[12];
    off[0] = 0;
    for (int i = 0; i < 11; i++) off[i + 1] = off[i] + (size_t)9 * (Lcip[i] / 16) * 4 * Lco[i];
    int total = (int)off[11];

    // ---- fused weight repack (one launch) + input planes ----
    WPtrs wp;
    wp.p[0] = wd[0]; wp.p[1] = wd[1]; wp.p[2] = wd[2]; wp.p[3] = wd[3]; wp.p[4] = wd[4];
    wp.p[5] = w_in;
    wp.p[6] = wu[0]; wp.p[7] = wu[1]; wp.p[8] = wu[2]; wp.p[9] = wu[3]; wp.p[10] = wu[4];
    repack_all<<<(total + 255) / 256, 256>>>(wp, W4, total);
    to_planes<<<(524288 + 255) / 256, 256>>>(x, Xhi, Xlo);

    // ---- encoder (MODE 0: DB=1, 2 CTAs/SM) ----
    conv_tc<0, 1, 2, 1><<<dim3(32, 16, 2), 256, BUF_M0>>>(Xhi, Xlo, W4 + off[0], bd[0], Ahi, Alo, nullptr, 2, 16, 64, 256, 256, 1);
    conv_tc<0, 1, 2, 1><<<dim3(16, 8, 4), 256, BUF_M0>>>(Ahi, Alo, W4 + off[1], bd[1], Bhi, Blo, nullptr, 2, 64, 128, 128, 128, 1);
    conv_tc<0, 1, 2, 1><<<dim3(8, 4, 8), 256, BUF_M0>>>(Bhi, Blo, W4 + off[2], bd[2], Ahi, Alo, nullptr, 2, 128, 256, 64, 64, 1);
    conv_tc<0, 2, 2, 1><<<dim3(8, 2, 16), 256, BUF_M0>>>(Ahi, Alo, W4 + off[3], nullptr, nullptr, nullptr, P, 2, 256, 512, 32, 32, 0);
    reduce_k_f16<<<(1048576 + 255) / 256, 256>>>(P, bd[3], Bhi, Blo, 2, 1048576, 512, 1);
    conv_tc<0, 4, 2, 1><<<dim3(8, 1, 32), 256, BUF_M0>>>(Bhi, Blo, W4 + off[4], nullptr, nullptr, nullptr, P, 2, 512, 1024, 16, 16, 0);
    reduce_k_f16<<<(524288 + 255) / 256, 256>>>(P, bd[4], Ahi, Alo, 4, 524288, 1024, 1);

    // ---- inner conv + BN + LReLU ----
    conv_tc<1, 4, 2, 2><<<dim3(8, 1, 32), 256, 2 * BUF_M1>>>(Ahi, Alo, W4 + off[5], nullptr, nullptr, nullptr, P, 2, 1024, 1024, 16, 16, 0);
    reduce_k_f32<<<(524288 + 255) / 256, 256>>>(P, b_in, C, 4, 524288, 1024);
    bn_stats<<<4, 256>>>(C, 512, 1024);
    bn_apply_f16<<<(524288 + 255) / 256, 256>>>(C, gamma, beta, Bhi, Blo, 1024, 524288);

    // ---- decoder ----
    conv_tc<2, 4, 2, 2><<<dim3(8, 1, 64), 256, 2 * BUF_M2>>>(Bhi, Blo, W4 + off[6], nullptr, nullptr, nullptr, P, 2, 1024, 512, 32, 32, 0);
    reduce_k_f16<<<(1048576 + 255) / 256, 256>>>(P, bu[0], Ahi, Alo, 4, 1048576, 512, 1);
    conv_tc<2, 1, 2, 2><<<dim3(4, 2, 32), 256, 2 * BUF_M2>>>(Ahi, Alo, W4 + off[7], bu[1], Bhi, Blo, nullptr, 2, 512, 256, 64, 64, 1);
    conv_tc<2, 1, 2, 2><<<dim3(8, 4, 16), 256, 2 * BUF_M2>>>(Bhi, Blo, W4 + off[8], bu[2], Ahi, Alo, nullptr, 2, 256, 128, 128, 128, 1);
    conv_tc<2, 1, 2, 2><<<dim3(16, 8, 8), 256, 2 * BUF_M2>>>(Ahi, Alo, W4 + off[9], bu[3], Bhi, Blo, nullptr, 2, 128, 64, 256, 256, 1);
    conv_tc<2, 1, 2, 2><<<dim3(32, 16, 8), 256, 2 * BUF_M2>>>(Bhi, Blo, W4 + off[10], bu[4], Ahi, Alo, nullptr, 2, 64, 64, 512, 512, 1);

    // ---- epilogue 1x1 (smem-staged, coalesced) ----
    ep_nhwc<<<524288 / 64, 256>>>(Ahi, Alo, wep, bep, outp);
}

// round 15
// speedup vs baseline: 2.0646x; 1.2513x over previous
#include <cuda_runtime.h>
#include <cuda_fp16.h>
#include <cstdint>

// ---------------------------------------------------------------------------
// Scratch (static __device__ globals; no allocation allowed)
// ---------------------------------------------------------------------------
__device__ float    g_bufA[33554432];   // ping: fp16 hi/lo planes (as halves)
__device__ float    g_bufB[33554432];   // pong
__device__ float    g_bufP[16777216];   // split-K fp32 partials
__device__ float    g_bufC[1048576];    // fp32 inner activations (BN input)
__device__ float    g_bufX[8388608];    // input hi/lo planes, C padded to 16
__device__ uint4    g_w4[5504256];      // fused B-fragment weights (hi,hi,lo,lo)
__device__ float    g_mean[1024];
__device__ float    g_rstd[1024];

// decoder parity-class tap tables (mode 2, PW = 9)
__constant__ int c_tcnt[4]    = {1, 2, 2, 4};
__constant__ int c_twid[4][4] = {{4,0,0,0},{3,5,0,0},{1,7,0,0},{0,2,6,8}};
__constant__ int c_toff[4][4] = {{0,0,0,0},{0,1,0,0},{0,9,0,0},{0,1,9,10}};

// fused-repack layer tables (element = one uint4 = 4 weights hi+lo)
__constant__ int rk_ci[11]  = {3, 64, 128, 256, 512, 1024, 1024, 512, 256, 128, 64};
__constant__ int rk_cip[11] = {16, 64, 128, 256, 512, 1024, 1024, 512, 256, 128, 64};
__constant__ int rk_co[11]  = {64, 128, 256, 512, 1024, 1024, 512, 256, 128, 64, 64};
// offsets: cumulative 9*(Cip/16)*4*Co per layer (VERIFIED against host off[])
__constant__ int rk_offs[12] = {0, 2304, 20736, 94464, 389376, 1569024, 3928320,
                                5107968, 5402880, 5476608, 5495040, 5504256};

__device__ __forceinline__ float lrelu(float v) { return v >= 0.f ? v : 0.01f * v; }

__device__ __forceinline__ void cp16(uint32_t dst, const void* src, int sz)
{
    asm volatile("cp.async.cg.shared.global [%0], [%1], 16, %2;"
                 :: "r"(dst), "l"(src), "r"(sz));
}
__device__ __forceinline__ void cp_commit()
{
    asm volatile("cp.async.commit_group;");
}
template <int N>
__device__ __forceinline__ void cp_wait_n()
{
    asm volatile("cp.async.wait_group %0;" :: "n"(N));
}

__device__ __forceinline__ void ldsm4(uint32_t& r0, uint32_t& r1, uint32_t& r2,
                                      uint32_t& r3, uint32_t addr)
{
    asm volatile("ldmatrix.sync.aligned.m8n8.x4.shared.b16 {%0,%1,%2,%3}, [%4];"
                 : "=r"(r0), "=r"(r1), "=r"(r2), "=r"(r3) : "r"(addr));
}

__device__ __forceinline__ void mma16816(float* acc, uint32_t a0, uint32_t a1,
                                         uint32_t a2, uint32_t a3, uint32_t b0, uint32_t b1)
{
    asm volatile("mma.sync.aligned.m16n8k16.row.col.f32.f16.f16.f32 "
                 "{%0,%1,%2,%3},{%4,%5,%6,%7},{%8,%9},{%0,%1,%2,%3};"
                 : "+f"(acc[0]), "+f"(acc[1]), "+f"(acc[2]), "+f"(acc[3])
                 : "r"(a0), "r"(a1), "r"(a2), "r"(a3), "r"(b0), "r"(b1));
}

__device__ __forceinline__ void split16(float v, __half& h, __half& l)
{
    h = __float2half_rn(v);
    l = __float2half_rn(v - __half2float(h));
}

// ---------------------------------------------------------------------------
// Tensor-core implicit-GEMM conv (NHWC fp16 hi/lo planes), 3-term fp16 split.
// MF = M-fragments per warp (tile M = 64*MF pixels). N tile = 64 co.
// DB = staging buffers (2 = cp.async double-buffered, 1 = single buffer).
// MODE 0: SAME conv + stride-2 subsample. Patch stored in EVEN/ODD column
//         planes so stride-2 A ldmatrix reads are conflict-free.
// MODE 1: SAME conv stride 1
// MODE 2: zero-insert up2 + SAME conv, one parity class per block
// Block: 256 thr = 8 warps (4 M x 2 N). K-chunk 16 channels.
// Weight smem uses a low-3-bit XOR swizzle ((cw&7)^(k2<<1)) so the B
// LDS.128 phases hit 8 distinct 16B bank-groups (was 4-way conflicted).
// ---------------------------------------------------------------------------
template <int MODE, int SPLIT, int MF, int DB>
__global__ void __launch_bounds__(256) conv_tc(
    const __half* __restrict__ inHi, const __half* __restrict__ inLo,
    const uint4* __restrict__ w4, const float* __restrict__ bias,
    __half* __restrict__ outHi, __half* __restrict__ outLo,
    float* __restrict__ outP,
    int NB, int Ci, int Co, int Hout, int Wout, int act)
{
    constexpr int PW   = (MODE == 0) ? 17 : ((MODE == 1) ? 10 : 9);
    constexpr int PH   = (MODE == 0) ? (16 * MF + 1) : ((MODE == 1) ? (8 * MF + 2) : (8 * MF + 1));
    constexpr int NPX  = PH * PW;
    constexpr int CSTR = 24;                       // halves per pixel row (16 used)
    constexpr int MAXT = (MODE == 2) ? 4 : 9;
    constexpr int MDEL = ((MODE == 0) ? 16 : 8) * PW * CSTR * 2;  // byte delta between M-fragments
    constexpr int PATB = NPX * CSTR * 2;           // one plane bytes
    constexpr int WOFF = 2 * PATB;                 // weights offset inside buffer
    constexpr int BUFSZ = WOFF + MAXT * 256 * 16;  // one staging buffer bytes

    extern __shared__ __align__(16) char smem[];

    const int tid  = threadIdx.x;
    const int lane = tid & 31, w = tid >> 5;
    const int g    = lane >> 2, tig = lane & 3;
    const int wm   = w & 3, wn = w >> 2;

    const int SX    = (MODE == 2) ? (Wout >> 4) : (Wout >> 3);
    const int sx    = blockIdx.x % SX;
    const int split = blockIdx.x / SX;
    const int sy    = blockIdx.y;
    const int gpc   = Co >> 6;
    int z = blockIdx.z;
    int cls = 0;
    if (MODE == 2) { cls = z / (NB * gpc); z -= cls * (NB * gpc); }
    const int n   = z / gpc;
    const int cob = (z - n * gpc) << 6;

    const int T = (MODE == 2) ? c_tcnt[cls] : 9;

    int Hin, Win, iy0, ix0;
    if (MODE == 0)      { Hin = Hout * 2; Win = Wout * 2; iy0 = sy * 16 * MF - 1; ix0 = sx * 16 - 1; }
    else if (MODE == 1) { Hin = Hout;     Win = Wout;     iy0 = sy * 8 * MF - 1;  ix0 = sx * 8 - 1; }
    else                { Hin = Hout / 2; Win = Wout / 2; iy0 = sy * 8 * MF;      ix0 = sx * 8; }

    // ldmatrix per-lane row address (patch-space pixel + k-half), fragment 0
    const int lr   = lane & 7;
    const int sel  = lane >> 3;
    const int row8 = sel & 1;
    const int kh2  = sel >> 1;
    int pix;
    if (MODE == 0) pix = (4 * wm + 2 * row8) * PW + lr;      // even-plane idx lr (col 2*lr)
    else           pix = (2 * wm + row8) * PW + lr;
    const uint32_t smem_a = (uint32_t)__cvta_generic_to_shared(smem);
    const uint32_t offb   = (uint32_t)((pix * CSTR + kh2 * 8) * 2);

    float acc[MF][4][4];
#pragma unroll
    for (int m = 0; m < MF; m++)
#pragma unroll
        for (int i = 0; i < 4; i++)
#pragma unroll
            for (int j = 0; j < 4; j++) acc[m][i][j] = 0.f;

    const int nch = Ci >> 4;
    const __half* inHiN = inHi + (size_t)n * Hin * Win * Ci;
    const __half* inLoN = inLo + (size_t)n * Hin * Win * Ci;

    int ciB = 0, nci = Ci;
    if (SPLIT > 1) { nci = Ci / SPLIT; ciB = split * nci; }
    const int nchunks = nci >> 4;

    // ---- staging (weights + patch for chunk cidx into buffer bsel) ----
    auto stage = [&](int cidx, int bsel) {
        const int ci0 = ciB + (cidx << 4);
        const int ch  = ci0 >> 4;
        const uint32_t base = smem_a + bsel * BUFSZ;
#pragma unroll 1
        for (int j = tid; j < T * 256; j += 256) {
            int t  = j >> 8;
            int r  = j & 255;
            int k2 = r >> 6;
            int cc = r & 63;
            int w9 = (MODE == 2) ? c_twid[cls][t] : t;
            const uint4* src = &w4[((size_t)(w9 * nch + ch) * 4 + k2) * Co + cob + cc];
            // bank-group swizzle: low 3 bits XOR (k2<<1)
            int pidx = (t << 8) + (k2 << 6) + ((cc & ~7) | ((cc & 7) ^ (k2 << 1)));
            cp16(base + WOFF + pidx * 16, src, 16);
        }
#pragma unroll 1
        for (int s = tid; s < NPX; s += 256) {
            int r = s / PW, c = s - r * PW;
            int iy = iy0 + r, ix = ix0 + c;
            bool ok = ((unsigned)iy < (unsigned)Hin) && ((unsigned)ix < (unsigned)Win);
            size_t gix = ((size_t)iy * Win + ix) * Ci + ci0;
            const __half* ph = ok ? (inHiN + gix) : inHiN;
            const __half* pl = ok ? (inLoN + gix) : inLoN;
            int sz = ok ? 16 : 0;
            // MODE 0: even/odd column-plane remap for conflict-free A ldmatrix
            int sdst = (MODE == 0) ? (r * PW + ((c & 1) ? 9 + (c >> 1) : (c >> 1))) : s;
            uint32_t dh = base + sdst * (CSTR * 2);
            uint32_t dl = base + PATB + sdst * (CSTR * 2);
            cp16(dh, ph, sz);      cp16(dh + 16, ph + 8, sz);
            cp16(dl, pl, sz);      cp16(dl + 16, pl + 8, sz);
        }
        cp_commit();
    };

    // ---- pipelined main loop ----
    stage(0, 0);
    const int gsw = g ^ (tig << 1);     // swizzled B lane column
#pragma unroll 1
    for (int c = 0; c < nchunks; c++) {
        const int bsel = (DB == 2) ? (c & 1) : 0;
        if (DB == 2 && c + 1 < nchunks) {
            stage(c + 1, (c + 1) & 1);
            cp_wait_n<1>();
        } else {
            cp_wait_n<0>();
        }
        __syncthreads();

        const uint32_t bbase = smem_a + bsel * BUFSZ;
        const uint4*  wbuf  = (const uint4*)(smem + bsel * BUFSZ + WOFF);

#pragma unroll
        for (int t = 0; t < MAXT; t++) {
            if (MODE == 2 && t >= T) break;
            uint32_t ab;
            if (MODE == 0) {
                // even/odd plane tap offsets: kw=0 -> even idx g (+0);
                // kw=1 -> odd plane (+9*CSTR); kw=2 -> even idx g+1 (+CSTR)
                const int kh = t / 3, kw = t % 3;
                ab = (uint32_t)((kh * PW + (kw == 0 ? 0 : (kw == 1 ? 9 : 1))) * CSTR * 2);
            } else {
                const int toff = (MODE == 2) ? c_toff[cls][t] : ((t / 3) * PW + (t % 3));
                ab = (uint32_t)(toff * CSTR * 2);
            }
            uint32_t ah[MF][4], al[MF][4];
#pragma unroll
            for (int m = 0; m < MF; m++) {
                ldsm4(ah[m][0], ah[m][1], ah[m][2], ah[m][3], bbase + offb + ab + m * MDEL);
                ldsm4(al[m][0], al[m][1], al[m][2], al[m][3], bbase + PATB + offb + ab + m * MDEL);
            }
            const uint4* wrow = wbuf + (t << 8) + (tig << 6);
#pragma unroll
            for (int sub = 0; sub < 4; sub++) {
                uint4 bq = wrow[wn * 32 + sub * 8 + gsw];
#pragma unroll
                for (int m = 0; m < MF; m++) {
                    mma16816(acc[m][sub], ah[m][0], ah[m][1], ah[m][2], ah[m][3], bq.x, bq.y);
                    mma16816(acc[m][sub], ah[m][0], ah[m][1], ah[m][2], ah[m][3], bq.z, bq.w);
                    mma16816(acc[m][sub], al[m][0], al[m][1], al[m][2], al[m][3], bq.x, bq.y);
                }
            }
        }
        __syncthreads();
        if (DB == 1 && c + 1 < nchunks) stage(c + 1, 0);
    }

    // ---- epilogue ----
    const int colb = cob + wn * 32 + 2 * tig;
#pragma unroll
    for (int m = 0; m < MF; m++) {
        int ohA, ohB, ow;
        if (MODE == 2) {
            int pr = cls >> 1, pc = cls & 1;
            int qr = sy * 8 * MF + 2 * wm + 8 * m;
            ohA = qr * 2 + pr;
            ohB = (qr + 1) * 2 + pr;
            ow  = (sx * 8 + g) * 2 + pc;
        } else {
            // block covers 8*MF OUTPUT rows in both MODE 0 and MODE 1
            ohA = sy * 8 * MF + 2 * wm + 8 * m;
            ohB = ohA + 1;
            ow  = sx * 8 + g;
        }
        if (SPLIT == 1) {
#pragma unroll
            for (int sub = 0; sub < 4; sub++) {
                int col = colb + sub * 8;
                float b0 = __ldg(&bias[col]), b1 = __ldg(&bias[col + 1]);
                float v0 = acc[m][sub][0] + b0, v1 = acc[m][sub][1] + b1;
                float v2 = acc[m][sub][2] + b0, v3 = acc[m][sub][3] + b1;
                if (act) { v0 = lrelu(v0); v1 = lrelu(v1); v2 = lrelu(v2); v3 = lrelu(v3); }
                __half h0, h1, h2, h3, l0, l1, l2, l3;
                split16(v0, h0, l0); split16(v1, h1, l1);
                split16(v2, h2, l2); split16(v3, h3, l3);
                size_t iA = (((size_t)n * Hout + ohA) * Wout + ow) * Co + col;
                size_t iB = (((size_t)n * Hout + ohB) * Wout + ow) * Co + col;
                *(__half2*)(outHi + iA) = __halves2half2(h0, h1);
                *(__half2*)(outHi + iB) = __halves2half2(h2, h3);
                *(__half2*)(outLo + iA) = __halves2half2(l0, l1);
                *(__half2*)(outLo + iB) = __halves2half2(l2, l3);
            }
        } else {
            float* po = outP + (size_t)split * ((size_t)NB * Hout * Wout * Co);
#pragma unroll
            for (int sub = 0; sub < 4; sub++) {
                int col = colb + sub * 8;
                float2* pA = (float2*)(po + (((size_t)n * Hout + ohA) * Wout + ow) * Co + col);
                float2* pB = (float2*)(po + (((size_t)n * Hout + ohB) * Wout + ow) * Co + col);
                *pA = make_float2(acc[m][sub][0], acc[m][sub][1]);
                *pB = make_float2(acc[m][sub][2], acc[m][sub][3]);
            }
        }
    }
}

// ---------------------------------------------------------------------------
// Fused weight repack for ALL layers in ONE launch.
// w [Co][Ci][3][3] -> fused B-fragment uint4 (hi pair, hi pair, lo pair, lo pair)
// ---------------------------------------------------------------------------
struct WPtrs { const float* p[11]; };

__global__ void repack_all(WPtrs wp, uint4* __restrict__ out, int total)
{
    int j = blockIdx.x * 256 + threadIdx.x;
    if (j >= total) return;
    int L = 0;
#pragma unroll
    for (int i = 1; i < 11; i++) if (j >= rk_offs[i]) L = i;
    int jj = j - rk_offs[L];
    int Ci = rk_ci[L], Cip = rk_cip[L], Co = rk_co[L];
    const float* w = wp.p[L];

    int co = jj % Co;
    int r  = jj / Co;
    int k4 = r & 3; r >>= 2;
    int nch = Cip >> 4;
    int ch  = r % nch;
    int t   = r / nch;
    int cbase = ch * 16 + 2 * k4;
    int cs[4] = {cbase, cbase + 1, cbase + 8, cbase + 9};
    __half h[4], l[4];
#pragma unroll
    for (int e = 0; e < 4; e++) {
        float v = (cs[e] < Ci) ? w[((size_t)co * Ci + cs[e]) * 9 + t] : 0.f;
        split16(v, h[e], l[e]);
    }
    uint4 o;
    o.x = (uint32_t)__half_as_ushort(h[0]) | ((uint32_t)__half_as_ushort(h[1]) << 16);
    o.y = (uint32_t)__half_as_ushort(h[2]) | ((uint32_t)__half_as_ushort(h[3]) << 16);
    o.z = (uint32_t)__half_as_ushort(l[0]) | ((uint32_t)__half_as_ushort(l[1]) << 16);
    o.w = (uint32_t)__half_as_ushort(l[2]) | ((uint32_t)__half_as_ushort(l[3]) << 16);
    out[j] = o;
}

// ---------------------------------------------------------------------------
// input transpose NCHW -> NHWC hi/lo planes, C=3 padded to 16
// ---------------------------------------------------------------------------
__global__ void to_planes(const float* __restrict__ x, __half* __restrict__ Xhi,
                          __half* __restrict__ Xlo)
{
    int i = blockIdx.x * 256 + threadIdx.x;
    if (i >= 2 * 512 * 512) return;
    int n = i >> 18;
    int p = i & 262143;
    union { __half h[16]; uint4 u[2]; } H, L;
#pragma unroll
    for (int e = 0; e < 16; e++) { H.h[e] = __ushort_as_half(0); L.h[e] = __ushort_as_half(0); }
#pragma unroll
    for (int c = 0; c < 3; c++) {
        float v = x[((size_t)n * 3 + c) * 262144 + p];
        split16(v, H.h[c], L.h[c]);
    }
    ((uint4*)Xhi)[(size_t)i * 2]     = H.u[0];
    ((uint4*)Xhi)[(size_t)i * 2 + 1] = H.u[1];
    ((uint4*)Xlo)[(size_t)i * 2]     = L.u[0];
    ((uint4*)Xlo)[(size_t)i * 2 + 1] = L.u[1];
}

// ---------------------------------------------------------------------------
// split-K reduces
// ---------------------------------------------------------------------------
__global__ void reduce_k_f16(const float* __restrict__ part, const float* __restrict__ bias,
                             __half* __restrict__ oh, __half* __restrict__ ol,
                             int S, int per, int Co, int act)
{
    int i = blockIdx.x * 256 + threadIdx.x;
    if (i >= per) return;
    float s = 0.f;
    for (int k = 0; k < S; k++) s += part[(size_t)k * per + i];
    float v = s + __ldg(&bias[i % Co]);
    if (act) v = lrelu(v);
    __half h, l;
    split16(v, h, l);
    oh[i] = h;
    ol[i] = l;
}

__global__ void reduce_k_f32(const float* __restrict__ part, const float* __restrict__ bias,
                             float* __restrict__ out, int S, int per, int Co)
{
    int i = blockIdx.x * 256 + threadIdx.x;
    if (i >= per) return;
    float s = 0.f;
    for (int k = 0; k < S; k++) s += part[(size_t)k * per + i];
    out[i] = s + __ldg(&bias[i % Co]);
}

// ---------------------------------------------------------------------------
// BatchNorm (batch stats) on fp32 NHWC, apply -> hi/lo planes
// ---------------------------------------------------------------------------
__global__ void bn_stats(const float* __restrict__ x, int rows, int C)
{
    int c = blockIdx.x * 256 + threadIdx.x;
    if (c >= C) return;
    float s = 0.f, s2 = 0.f;
    for (int r = 0; r < rows; r++) {
        float v = x[(size_t)r * C + c];
        s += v;
        s2 += v * v;
    }
    float m   = s / rows;
    float var = s2 / rows - m * m;
    g_mean[c] = m;
    g_rstd[c] = rsqrtf(var + 1e-5f);
}

__global__ void bn_apply_f16(const float* __restrict__ x, const float* __restrict__ gamma,
                             const float* __restrict__ beta, __half* __restrict__ oh,
                             __half* __restrict__ ol, int C, int total)
{
    int i = blockIdx.x * 256 + threadIdx.x;
    if (i >= total) return;
    int c = i % C;
    float v = (x[i] - g_mean[c]) * g_rstd[c] * __ldg(&gamma[c]) + __ldg(&beta[c]);
    v = lrelu(v);
    __half h, l;
    split16(v, h, l);
    oh[i] = h;
    ol[i] = l;
}

// ---------------------------------------------------------------------------
// Epilogue: 1x1 conv 64->3, hi/lo planes in -> NCHW fp32 out
// smem-staged: block handles 64 pixels; coalesced uint4 global loads;
// 4 threads/pixel (16ch each) + shfl reduce.
// ---------------------------------------------------------------------------
__global__ void __launch_bounds__(256) ep_nhwc(
    const __half* __restrict__ ih, const __half* __restrict__ il,
    const float* __restrict__ w, const float* __restrict__ b,
    float* __restrict__ out)
{
    __shared__ float  s_w[192];
    __shared__ __half s_h[64 * 72];   // 72-halves stride (bank spread)
    __shared__ __half s_l[64 * 72];

    const int tid = threadIdx.x;
    const size_t p0 = (size_t)blockIdx.x * 64;   // first pixel of this block

    if (tid < 192) s_w[tid] = w[tid];
    // coalesced copy: 64 px * 8 uint4 per plane
    const uint4* srcH = (const uint4*)(ih + p0 * 64);
    const uint4* srcL = (const uint4*)(il + p0 * 64);
#pragma unroll
    for (int j = tid; j < 512; j += 256) {
        int px = j >> 3, q = j & 7;
        *(uint4*)(s_h + px * 72 + q * 8) = srcH[j];
        *(uint4*)(s_l + px * 72 + q * 8) = srcL[j];
    }
    __syncthreads();

    const int px = tid >> 2;      // 0..63
    const int qt = tid & 3;       // 16-channel quarter
    const __half* ph = s_h + px * 72 + qt * 16;
    const __half* pl = s_l + px * 72 + qt * 16;
    float a0 = 0.f, a1 = 0.f, a2 = 0.f;
#pragma unroll
    for (int c = 0; c < 16; c++) {
        float v = __half2float(ph[c]) + __half2float(pl[c]);
        int cc = qt * 16 + c;
        a0 += v * s_w[cc];
        a1 += v * s_w[64 + cc];
        a2 += v * s_w[128 + cc];
    }
#pragma unroll
    for (int o = 1; o < 4; o <<= 1) {
        a0 += __shfl_xor_sync(0xffffffff, a0, o);
        a1 += __shfl_xor_sync(0xffffffff, a1, o);
        a2 += __shfl_xor_sync(0xffffffff, a2, o);
    }
    if (qt == 0) {
        size_t i = p0 + px;
        int n = (int)(i >> 18);
        int p = (int)(i & 262143);
        out[((size_t)n * 3 + 0) * 262144 + p] = a0 + __ldg(&b[0]);
        out[((size_t)n * 3 + 1) * 262144 + p] = a1 + __ldg(&b[1]);
        out[((size_t)n * 3 + 2) * 262144 + p] = a2 + __ldg(&b[2]);
    }
}

// ---------------------------------------------------------------------------
// Launch sequence
// ---------------------------------------------------------------------------
// per-buffer sizes: patches(hi+lo) + weights
static const int BUF_M0 = (33 * 17) * 24 * 2 * 2 + 9 * 256 * 16;   // 90720
static const int BUF_M1 = (18 * 10) * 24 * 2 * 2 + 9 * 256 * 16;   // 54144
static const int BUF_M2 = (17 * 9)  * 24 * 2 * 2 + 4 * 256 * 16;   // 31072

extern "C" void kernel_launch(void* const* d_in, const int* in_sizes, int n_in,
                              void* d_out, int out_size)
{
    (void)in_sizes; (void)n_in; (void)out_size;
    const float* x     = (const float*)d_in[0];
    const float* wd[5] = {(const float*)d_in[1], (const float*)d_in[3], (const float*)d_in[5],
                          (const float*)d_in[7], (const float*)d_in[9]};
    const float* bd[5] = {(const float*)d_in[2], (const float*)d_in[4], (const float*)d_in[6],
                          (const float*)d_in[8], (const float*)d_in[10]};
    const float* w_in  = (const float*)d_in[11];
    const float* b_in  = (const float*)d_in[12];
    const float* gamma = (const float*)d_in[13];
    const float* beta  = (const float*)d_in[14];
    const float* wu[5] = {(const float*)d_in[15], (const float*)d_in[17], (const float*)d_in[19],
                          (const float*)d_in[21], (const float*)d_in[23]};
    const float* bu[5] = {(const float*)d_in[16], (const float*)d_in[18], (const float*)d_in[20],
                          (const float*)d_in[22], (const float*)d_in[24]};
    const float* wep = (const float*)d_in[25];
    const float* bep = (const float*)d_in[26];
    float* outp = (float*)d_out;

    float *A, *B, *P, *C, *X;
    uint4* W4;
    cudaGetSymbolAddress((void**)&A, g_bufA);
    cudaGetSymbolAddress((void**)&B, g_bufB);
    cudaGetSymbolAddress((void**)&P, g_bufP);
    cudaGetSymbolAddress((void**)&C, g_bufC);
    cudaGetSymbolAddress((void**)&X, g_bufX);
    cudaGetSymbolAddress((void**)&W4, g_w4);

    __half* Ahi = (__half*)A;  __half* Alo = Ahi + 33554432;
    __half* Bhi = (__half*)B;  __half* Blo = Bhi + 33554432;
    __half* Xhi = (__half*)X;  __half* Xlo = Xhi + 8388608;

    cudaFuncSetAttribute(conv_tc<0, 1, 2, 1>, cudaFuncAttributeMaxDynamicSharedMemorySize, BUF_M0);
    cudaFuncSetAttribute(conv_tc<0, 2, 2, 1>, cudaFuncAttributeMaxDynamicSharedMemorySize, BUF_M0);
    cudaFuncSetAttribute(conv_tc<0, 4, 2, 1>, cudaFuncAttributeMaxDynamicSharedMemorySize, BUF_M0);
    cudaFuncSetAttribute(conv_tc<1, 4, 2, 2>, cudaFuncAttributeMaxDynamicSharedMemorySize, 2 * BUF_M1);
    cudaFuncSetAttribute(conv_tc<2, 1, 2, 2>, cudaFuncAttributeMaxDynamicSharedMemorySize, 2 * BUF_M2);
    cudaFuncSetAttribute(conv_tc<2, 4, 2, 2>, cudaFuncAttributeMaxDynamicSharedMemorySize, 2 * BUF_M2);

    // layer weight offsets (must match rk_offs): 9*(Cip/16)*4*Co
    const int Lcip[11] = {16, 64, 128, 256, 512, 1024, 1024, 512, 256, 128, 64};
    const int Lco[11]  = {64, 128, 256, 512, 1024, 1024, 512, 256, 128, 64, 64};
    size_t off[12];
    off[0] = 0;
    for (int i = 0; i < 11; i++) off[i + 1] = off[i] + (size_t)9 * (Lcip[i] / 16) * 4 * Lco[i];
    int total = (int)off[11];

    // ---- fused weight repack (one launch) + input planes ----
    WPtrs wp;
    wp.p[0] = wd[0]; wp.p[1] = wd[1]; wp.p[2] = wd[2]; wp.p[3] = wd[3]; wp.p[4] = wd[4];
    wp.p[5] = w_in;
    wp.p[6] = wu[0]; wp.p[7] = wu[1]; wp.p[8] = wu[2]; wp.p[9] = wu[3]; wp.p[10] = wu[4];
    repack_all<<<(total + 255) / 256, 256>>>(wp, W4, total);
    to_planes<<<(524288 + 255) / 256, 256>>>(x, Xhi, Xlo);

    // ---- encoder (MODE 0: DB=1, 2 CTAs/SM) ----
    conv_tc<0, 1, 2, 1><<<dim3(32, 16, 2), 256, BUF_M0>>>(Xhi, Xlo, W4 + off[0], bd[0], Ahi, Alo, nullptr, 2, 16, 64, 256, 256, 1);
    conv_tc<0, 1, 2, 1><<<dim3(16, 8, 4), 256, BUF_M0>>>(Ahi, Alo, W4 + off[1], bd[1], Bhi, Blo, nullptr, 2, 64, 128, 128, 128, 1);
    conv_tc<0, 1, 2, 1><<<dim3(8, 4, 8), 256, BUF_M0>>>(Bhi, Blo, W4 + off[2], bd[2], Ahi, Alo, nullptr, 2, 128, 256, 64, 64, 1);
    conv_tc<0, 2, 2, 1><<<dim3(8, 2, 16), 256, BUF_M0>>>(Ahi, Alo, W4 + off[3], nullptr, nullptr, nullptr, P, 2, 256, 512, 32, 32, 0);
    reduce_k_f16<<<(1048576 + 255) / 256, 256>>>(P, bd[3], Bhi, Blo, 2, 1048576, 512, 1);
    conv_tc<0, 4, 2, 1><<<dim3(8, 1, 32), 256, BUF_M0>>>(Bhi, Blo, W4 + off[4], nullptr, nullptr, nullptr, P, 2, 512, 1024, 16, 16, 0);
    reduce_k_f16<<<(524288 + 255) / 256, 256>>>(P, bd[4], Ahi, Alo, 4, 524288, 1024, 1);

    // ---- inner conv + BN + LReLU ----
    conv_tc<1, 4, 2, 2><<<dim3(8, 1, 32), 256, 2 * BUF_M1>>>(Ahi, Alo, W4 + off[5], nullptr, nullptr, nullptr, P, 2, 1024, 1024, 16, 16, 0);
    reduce_k_f32<<<(524288 + 255) / 256, 256>>>(P, b_in, C, 4, 524288, 1024);
    bn_stats<<<4, 256>>>(C, 512, 1024);
    bn_apply_f16<<<(524288 + 255) / 256, 256>>>(C, gamma, beta, Bhi, Blo, 1024, 524288);

    // ---- decoder ----
    conv_tc<2, 4, 2, 2><<<dim3(8, 1, 64), 256, 2 * BUF_M2>>>(Bhi, Blo, W4 + off[6], nullptr, nullptr, nullptr, P, 2, 1024, 512, 32, 32, 0);
    reduce_k_f16<<<(1048576 + 255) / 256, 256>>>(P, bu[0], Ahi, Alo, 4, 1048576, 512, 1);
    conv_tc<2, 1, 2, 2><<<dim3(4, 2, 32), 256, 2 * BUF_M2>>>(Ahi, Alo, W4 + off[7], bu[1], Bhi, Blo, nullptr, 2, 512, 256, 64, 64, 1);
    conv_tc<2, 1, 2, 2><<<dim3(8, 4, 16), 256, 2 * BUF_M2>>>(Bhi, Blo, W4 + off[8], bu[2], Ahi, Alo, nullptr, 2, 256, 128, 128, 128, 1);
    conv_tc<2, 1, 2, 2><<<dim3(16, 8, 8), 256, 2 * BUF_M2>>>(Ahi, Alo, W4 + off[9], bu[3], Bhi, Blo, nullptr, 2, 128, 64, 256, 256, 1);
    conv_tc<2, 1, 2, 2><<<dim3(32, 16, 8), 256, 2 * BUF_M2>>>(Bhi, Blo, W4 + off[10], bu[4], Ahi, Alo, nullptr, 2, 64, 64, 512, 512, 1);

    // ---- epilogue 1x1 (smem-staged, coalesced) ----
    ep_nhwc<<<524288 / 64, 256>>>(Ahi, Alo, wep, bep, outp);
}